// round 8
// baseline (speedup 1.0000x reference)
#include <cuda_runtime.h>
#include <cuda_fp16.h>

// DigitCaps routing:
//   x [128,1024,16], W [1,16,1024,16,16], B [16,1,1024] -> out [128,16,16] (fp32)

#define BATCH  128
#define NCAPS  16
#define INCAPS 1024
#define DIMC   16
#define COEF   0.25f

#define K1_CB     8
#define K1_NCBLK  128
#define K2_CT     32
#define K2_SPLIT  16
#define K2_TILES  2    // 1024 / (32*16)

#define RED_STRIDE 289   // u32 row stride for red[c_loc][...]: 289 = 9*32+1

typedef unsigned long long u64;
typedef unsigned int u32;

__device__ __forceinline__ u64 f2fma(u64 a, u64 b, u64 c) {
    u64 d;
    asm("fma.rn.f32x2 %0, %1, %2, %3;" : "=l"(d) : "l"(a), "l"(b), "l"(c));
    return d;
}

__device__ __forceinline__ u32 h2_bits(__half2 h) {
    union { __half2 h; u32 u; } cv;
    cv.h = h;
    return cv.u;
}

// scratch
__device__ __half g_uhat[(size_t)BATCH * NCAPS * INCAPS * DIMC];    // [b][n][c][d] fp16, 64 MB
__device__ float  g_part[(size_t)K1_NCBLK * BATCH * NCAPS * DIMC];  // [cblk][b][n*16+d], 16 MB
__device__ float  g_usum[(size_t)BATCH * NCAPS * DIMC];             // 128 KB
__device__ float  g_spart[(size_t)K2_SPLIT * BATCH * NCAPS * DIMC]; // 2 MB

// ---------------------------------------------------------------------------
// Kernel 1: grid (128 cblk, 16 n), 256 threads = 8 warps.
// warp = c (one c per warp), lane = b, 4 bt iterations of 32 b.
// W reads: warp-broadcast LDS.128. x: gmem->regs double-buffered.
// u_hat store COALESCED via smem transpose (red): each STG.128 spans 4 lines.
// Single-bt live set ~80 regs: no spills.
// ---------------------------------------------------------------------------
__global__ __launch_bounds__(256) void k1_uhat(const float* __restrict__ x,
                                               const float* __restrict__ W) {
    __shared__ float ws[2048];              // [8c][16d][16i], 8 KB
    __shared__ u32   red[8 * RED_STRIDE];   // [c_loc][l*9+dp] half2, 9.25 KB

    const int t = threadIdx.x;
    const int w = t >> 5;        // c-local = warp id (0..7)
    const int l = t & 31;        // b lane
    const int cblk = blockIdx.x;
    const int n    = blockIdx.y;
    const int c0   = cblk * K1_CB;
    const int c    = c0 + w;

    // --- load W tile (512 float4, linear, conflict-free)
    const float4* Wg4 = (const float4*)W;
    float4* ws4 = (float4*)ws;
    const int wb4 = n * 65536 + c0 * 64;
    ws4[t]       = Wg4[wb4 + t];
    ws4[t + 256] = Wg4[wb4 + t + 256];

    const float4* xg4 = (const float4*)x;
    uint4* ug = (uint4*)g_uhat;
    const float* wsc = ws + w * 256;

    union F4Q { float4 f[4]; u64 q[8]; };
    F4Q Xc, Xn;
#pragma unroll
    for (int k = 0; k < 4; k++) Xc.f[k] = xg4[l * 4096 + c * 4 + k];
    __syncthreads();   // ws ready

#pragma unroll
    for (int bt = 0; bt < 4; bt++) {
        const int b0 = bt * 32;

        // prefetch next bt (overlaps compute)
        if (bt < 3) {
#pragma unroll
            for (int k = 0; k < 4; k++)
                Xn.f[k] = xg4[(b0 + 32 + l) * 4096 + c * 4 + k];
        }

        // --- compute u_hat[b=l][c][d0..15] as 8 half2
        u32 out[8];
#pragma unroll
        for (int dp = 0; dp < 8; dp++) {
            float vh0, vh1;
#pragma unroll
            for (int h = 0; h < 2; h++) {
                const int d = dp * 2 + h;
                F4Q Wv;
                Wv.f[0] = *(const float4*)&wsc[d * 16 + 0];
                Wv.f[1] = *(const float4*)&wsc[d * 16 + 4];
                Wv.f[2] = *(const float4*)&wsc[d * 16 + 8];
                Wv.f[3] = *(const float4*)&wsc[d * 16 + 12];
                u64 sA = f2fma(Xc.q[0], Wv.q[0], 0ULL);
                u64 sB = f2fma(Xc.q[1], Wv.q[1], 0ULL);
                sA = f2fma(Xc.q[2], Wv.q[2], sA);
                sB = f2fma(Xc.q[3], Wv.q[3], sB);
                sA = f2fma(Xc.q[4], Wv.q[4], sA);
                sB = f2fma(Xc.q[5], Wv.q[5], sB);
                sA = f2fma(Xc.q[6], Wv.q[6], sA);
                sB = f2fma(Xc.q[7], Wv.q[7], sB);
                float2 fa = *(float2*)&sA;
                float2 fb = *(float2*)&sB;
                float v = (fa.x + fa.y) + (fb.x + fb.y);
                if (h == 0) vh0 = v; else vh1 = v;
            }
            out[dp] = h2_bits(__floats2half2_rn(vh0, vh1));
        }

        // --- stage into red: [c_loc=w][l*9+dp]  (9 mod 32: conflict-free)
#pragma unroll
        for (int q = 0; q < 8; q++) red[w * RED_STRIDE + l * 9 + q] = out[q];
        __syncthreads();

        // --- consumer A: coalesced u_hat store (512 uint4, 2 per thread)
#pragma unroll
        for (int k = 0; k < 2; k++) {
            int q = t + 256 * k;
            int b_loc = q >> 4;             // 0..31
            int ch    = q & 15;
            int c_loc = ch >> 1;            // 0..7
            int dh    = ch & 1;             // d-half
            const u32* rp = &red[c_loc * RED_STRIDE + b_loc * 9 + dh * 4];
            uint4 v = make_uint4(rp[0], rp[1], rp[2], rp[3]);
            size_t gi = ((size_t)((b0 + b_loc) * 16 + n) * 1024 + c0 + c_loc) * 2 + dh;
            ug[gi] = v;
        }

        // --- consumer B: c-partial reduction -> g_part
        {
            const int b2 = t >> 3, dp2 = t & 7;
            float s0 = 0.f, s1 = 0.f;
#pragma unroll
            for (int w2 = 0; w2 < 8; w2++) {
                __half2 hv = *(__half2*)&red[w2 * RED_STRIDE + b2 * 9 + dp2];
                float2 f = __half22float2(hv);
                s0 += f.x; s1 += f.y;
            }
            *(float2*)&g_part[cblk * 32768 + (b0 + b2) * 256 + n * 16 + dp2 * 2] =
                make_float2(s0, s1);
        }
        __syncthreads();   // red free for next bt

        Xc = Xn;
    }
}

// ---------------------------------------------------------------------------
// k_usum: grid 128 (b), 256 threads: usum[b][nd] = sum of 128 cblk partials
// ---------------------------------------------------------------------------
__global__ __launch_bounds__(256) void k_usum() {
    const int t = threadIdx.x, b = blockIdx.x;
    const float* p = g_part + b * 256 + t;
    float a0 = 0, a1 = 0, a2 = 0, a3 = 0;
#pragma unroll
    for (int k = 0; k < K1_NCBLK; k += 4) {
        a0 += p[(size_t)(k + 0) * 32768];
        a1 += p[(size_t)(k + 1) * 32768];
        a2 += p[(size_t)(k + 2) * 32768];
        a3 += p[(size_t)(k + 3) * 32768];
    }
    g_usum[b * 256 + t] = (a0 + a1) + (a2 + a3);
}

// ---------------------------------------------------------------------------
// k2a: grid (128 b, 16 csplit), 256 threads, 2 tiles of 32 c.
// uhs kept fp16 in smem (uint4 slots, c-stride 3, n-stride 97) -> 24.8 KB.
// ---------------------------------------------------------------------------
__global__ __launch_bounds__(256) void k2a_route(const float* __restrict__ Bb) {
    __shared__ uint4 uhs[16 * 97];
    __shared__ float sco[544];
    __shared__ float wbf[544];

    const int t  = threadIdx.x;
    const int b  = blockIdx.x;
    const int cs = blockIdx.y;

    const int sn = t >> 4, scs = t & 15;
    float ur[16];
#pragma unroll
    for (int j = 0; j < 16; j++) ur[j] = g_usum[b * 256 + sn * 16 + j];

    const int asp = t >> 6, an = (t >> 2) & 15, adq = t & 3;
    float sacc0 = 0, sacc1 = 0, sacc2 = 0, sacc3 = 0;

    const uint4* ug = (const uint4*)g_uhat;

    int ld_nn[4], ld_cl[4], ld_dh[4];
#pragma unroll
    for (int k = 0; k < 4; k++) {
        int flat = (t + 256 * k) * 8;
        ld_nn[k] = flat >> 9;
        ld_cl[k] = (flat >> 4) & 31;
        ld_dh[k] = (flat >> 3) & 1;
    }

    uint4 pv[4];
    {
        const int cb = cs * 64;
#pragma unroll
        for (int k = 0; k < 4; k++)
            pv[k] = ug[((size_t)(b * 16 + ld_nn[k]) * 1024 + cb + ld_cl[k]) * 2 + ld_dh[k]];
    }

#pragma unroll
    for (int tile = 0; tile < K2_TILES; tile++) {
        const int cb = cs * 64 + tile * K2_CT;
        __syncthreads();

#pragma unroll
        for (int k = 0; k < 4; k++)
            uhs[ld_nn[k] * 97 + ld_cl[k] * 3 + ld_dh[k]] = pv[k];
        __syncthreads();

        if (tile + 1 < K2_TILES) {
            const int cbn = cb + K2_CT;
#pragma unroll
            for (int k = 0; k < 4; k++)
                pv[k] = ug[((size_t)(b * 16 + ld_nn[k]) * 1024 + cbn + ld_cl[k]) * 2 + ld_dh[k]];
        }

        // --- scores
#pragma unroll
        for (int p = 0; p < 2; p++) {
            int cx = scs + p * 16;
            uint4 ua = uhs[sn * 97 + cx * 3 + 0];
            uint4 ub = uhs[sn * 97 + cx * 3 + 1];
            const __half2* ha = (const __half2*)&ua;
            const __half2* hb = (const __half2*)&ub;
            float dot = 0.f;
#pragma unroll
            for (int j = 0; j < 4; j++) {
                float2 fa = __half22float2(ha[j]);
                float2 fb = __half22float2(hb[j]);
                dot += fa.x * ur[2 * j] + fa.y * ur[2 * j + 1];
                dot += fb.x * ur[8 + 2 * j] + fb.y * ur[9 + 2 * j];
            }
            sco[cx * 17 + sn] = COEF * dot;
        }
        __syncthreads();

        // --- softmax over n + add B
        if (t < 32) {
            int cx = t;
            float v[16];
            float m = -1e30f;
#pragma unroll
            for (int nn = 0; nn < 16; nn++) { v[nn] = sco[cx * 17 + nn]; m = fmaxf(m, v[nn]); }
            float s = 0.f;
#pragma unroll
            for (int nn = 0; nn < 16; nn++) { v[nn] = expf(v[nn] - m); s += v[nn]; }
            float inv = 1.0f / s;
#pragma unroll
            for (int nn = 0; nn < 16; nn++)
                wbf[cx * 17 + nn] = v[nn] * inv + Bb[nn * 1024 + cb + cx];
        }
        __syncthreads();

        // --- weighted accumulate
        const __half2* uh2 = (const __half2*)uhs;
#pragma unroll
        for (int j = 0; j < 8; j++) {
            int cc2 = asp * 8 + j;
            float wv = wbf[cc2 * 17 + an];
            int h2i = (an * 97 + cc2 * 3) * 4 + adq * 2;
            float2 f0 = __half22float2(uh2[h2i]);
            float2 f1 = __half22float2(uh2[h2i + 1]);
            sacc0 += wv * f0.x; sacc1 += wv * f0.y;
            sacc2 += wv * f1.x; sacc3 += wv * f1.y;
        }
    }
    __syncthreads();

    float* spart = (float*)uhs;
    *(float4*)&spart[asp * 256 + an * 16 + adq * 4] = make_float4(sacc0, sacc1, sacc2, sacc3);
    __syncthreads();
    g_spart[cs * 32768 + b * 256 + t] =
        spart[t] + spart[256 + t] + spart[512 + t] + spart[768 + t];
}

// ---------------------------------------------------------------------------
// k2b: reduce 16 csplits, squash, write out
// ---------------------------------------------------------------------------
__global__ __launch_bounds__(256) void k2b_finish(float* __restrict__ out) {
    __shared__ float sfin[256];
    __shared__ float scale[16];
    const int t = threadIdx.x, b = blockIdx.x;

    const float* p = g_spart + b * 256 + t;
    float a0 = 0, a1 = 0, a2 = 0, a3 = 0;
#pragma unroll
    for (int k = 0; k < K2_SPLIT; k += 4) {
        a0 += p[(k + 0) * 32768];
        a1 += p[(k + 1) * 32768];
        a2 += p[(k + 2) * 32768];
        a3 += p[(k + 3) * 32768];
    }
    sfin[t] = (a0 + a1) + (a2 + a3);
    __syncthreads();

    if (t < 16) {
        float sq = 0.f;
#pragma unroll
        for (int d = 0; d < 16; d++) { float z = sfin[t * 16 + d]; sq += z * z; }
        float norm = sqrtf(sq);
        scale[t] = (1.0f - expf(-norm)) * rsqrtf(sq + 1e-8f);
    }
    __syncthreads();

    out[b * 256 + t] = scale[t >> 4] * sfin[t];
}

// ---------------------------------------------------------------------------
extern "C" void kernel_launch(void* const* d_in, const int* in_sizes, int n_in,
                              void* d_out, int out_size) {
    const float* x = (const float*)d_in[0];
    const float* W = (const float*)d_in[1];
    const float* B = (const float*)d_in[2];
    float* out = (float*)d_out;

    k1_uhat<<<dim3(K1_NCBLK, NCAPS), 256>>>(x, W);
    k_usum<<<BATCH, 256>>>();
    k2a_route<<<dim3(BATCH, K2_SPLIT), 256>>>(B);
    k2b_finish<<<BATCH, 256>>>(out);
}

// round 10
// speedup vs baseline: 1.1803x; 1.1803x over previous
#include <cuda_runtime.h>
#include <cuda_fp16.h>

// DigitCaps routing:
//   x [128,1024,16], W [1,16,1024,16,16], B [16,1,1024] -> out [128,16,16] (fp32)

#define BATCH  128
#define NCAPS  16
#define INCAPS 1024
#define DIMC   16
#define COEF   0.25f

#define K1_CB     8
#define K1_NCBLK  128
#define K2_CT     32
#define K2_SPLIT  16
#define K2_TILES  2    // 1024 / (32*16)

#define RED_STRIDE 289   // u32 row stride for red[c_loc][...]
#define XS_STRIDE  132   // float row stride for xs[b_loc][...] (128 + 4 pad)

typedef unsigned long long u64;
typedef unsigned int u32;

__device__ __forceinline__ u64 f2fma(u64 a, u64 b, u64 c) {
    u64 d;
    asm("fma.rn.f32x2 %0, %1, %2, %3;" : "=l"(d) : "l"(a), "l"(b), "l"(c));
    return d;
}

__device__ __forceinline__ u32 h2_bits(__half2 h) {
    union { __half2 h; u32 u; } cv;
    cv.h = h;
    return cv.u;
}

// scratch
__device__ __half g_uhat[(size_t)BATCH * NCAPS * INCAPS * DIMC];    // [b][n][c][d] fp16, 64 MB
__device__ float  g_part[(size_t)K1_NCBLK * BATCH * NCAPS * DIMC];  // [cblk][b][n*16+d], 16 MB
__device__ float  g_usum[(size_t)BATCH * NCAPS * DIMC];             // 128 KB
__device__ float  g_spart[(size_t)K2_SPLIT * BATCH * NCAPS * DIMC]; // 2 MB

// ---------------------------------------------------------------------------
// Kernel 1: grid (128 cblk, 16 n), 256 threads = 8 warps.
// warp = c (one c per warp), lane = b, 4 bt iterations of 32 b.
// x: cooperative COALESCED gmem->smem (4 lines/LDG), compute reads conflict-free.
// W reads: warp-broadcast LDS.128. u_hat store coalesced via red transpose.
// ---------------------------------------------------------------------------
__global__ __launch_bounds__(256) void k1_uhat(const float* __restrict__ x,
                                               const float* __restrict__ W) {
    __shared__ float ws[2048];                 // [8c][16d][16i], 8 KB
    __shared__ float xs[32 * XS_STRIDE];       // [32b][8c*16i + pad], 16.9 KB
    __shared__ u32   red[8 * RED_STRIDE];      // [c_loc][l*9+dp] half2, 9.25 KB

    const int t = threadIdx.x;
    const int w = t >> 5;        // c-local = warp id (0..7)
    const int l = t & 31;        // b lane
    const int cblk = blockIdx.x;
    const int n    = blockIdx.y;
    const int c0   = cblk * K1_CB;

    // --- load W tile (512 float4, linear, coalesced, conflict-free)
    const float4* Wg4 = (const float4*)W;
    float4* ws4 = (float4*)ws;
    const int wb4 = n * 65536 + c0 * 64;
    ws4[t]       = Wg4[wb4 + t];
    ws4[t + 256] = Wg4[wb4 + t + 256];

    const float4* xg4 = (const float4*)x;
    uint4* ug = (uint4*)g_uhat;
    const float* wsc = ws + w * 256;

    // coalesced x-load mapping: q = t + 256k -> b_loc = q>>5, off = q&31
    // gmem row per b: x[b][c0:c0+8][:] = 32 contiguous float4
    float4 P[4];
#pragma unroll
    for (int k = 0; k < 4; k++) {
        int q = t + 256 * k;
        P[k] = xg4[(q >> 5) * 4096 + c0 * 4 + (q & 31)];
    }

    union F4Q { float4 f[4]; u64 q[8]; };

#pragma unroll
    for (int bt = 0; bt < 4; bt++) {
        const int b0 = bt * 32;

        // --- stage prefetched x into xs (STS.128 conflict-free)
#pragma unroll
        for (int k = 0; k < 4; k++) {
            int q = t + 256 * k;
            *(float4*)&xs[(q >> 5) * XS_STRIDE + (q & 31) * 4] = P[k];
        }
        __syncthreads();   // xs (+ws on bt0) ready; prev red consumed

        // --- prefetch next bt (coalesced, overlaps compute)
        if (bt < 3) {
#pragma unroll
            for (int k = 0; k < 4; k++) {
                int q = t + 256 * k;
                P[k] = xg4[(b0 + 32 + (q >> 5)) * 4096 + c0 * 4 + (q & 31)];
            }
        }

        // --- own x row from smem (conflict-free: banks 4l+16w+4j)
        F4Q Xc;
#pragma unroll
        for (int k = 0; k < 4; k++)
            Xc.f[k] = *(const float4*)&xs[l * XS_STRIDE + w * 16 + k * 4];

        // --- compute u_hat[b=l][c=c0+w][d0..15] as 8 half2
        u32 out[8];
#pragma unroll
        for (int dp = 0; dp < 8; dp++) {
            float vh0, vh1;
#pragma unroll
            for (int h = 0; h < 2; h++) {
                const int d = dp * 2 + h;
                F4Q Wv;
                Wv.f[0] = *(const float4*)&wsc[d * 16 + 0];
                Wv.f[1] = *(const float4*)&wsc[d * 16 + 4];
                Wv.f[2] = *(const float4*)&wsc[d * 16 + 8];
                Wv.f[3] = *(const float4*)&wsc[d * 16 + 12];
                u64 sA = f2fma(Xc.q[0], Wv.q[0], 0ULL);
                u64 sB = f2fma(Xc.q[1], Wv.q[1], 0ULL);
                sA = f2fma(Xc.q[2], Wv.q[2], sA);
                sB = f2fma(Xc.q[3], Wv.q[3], sB);
                sA = f2fma(Xc.q[4], Wv.q[4], sA);
                sB = f2fma(Xc.q[5], Wv.q[5], sB);
                sA = f2fma(Xc.q[6], Wv.q[6], sA);
                sB = f2fma(Xc.q[7], Wv.q[7], sB);
                float2 fa = *(float2*)&sA;
                float2 fb = *(float2*)&sB;
                float v = (fa.x + fa.y) + (fb.x + fb.y);
                if (h == 0) vh0 = v; else vh1 = v;
            }
            out[dp] = h2_bits(__floats2half2_rn(vh0, vh1));
        }

        // --- stage into red (9 mod 32: conflict-free)
#pragma unroll
        for (int q = 0; q < 8; q++) red[w * RED_STRIDE + l * 9 + q] = out[q];
        __syncthreads();   // red ready (xs also fully read)

        // --- consumer A: coalesced u_hat store (512 uint4, 2/thread, 4 lines/instr)
#pragma unroll
        for (int k = 0; k < 2; k++) {
            int q = t + 256 * k;
            int b_loc = q >> 4;
            int ch    = q & 15;
            int c_loc = ch >> 1;
            int dh    = ch & 1;
            const u32* rp = &red[c_loc * RED_STRIDE + b_loc * 9 + dh * 4];
            uint4 v = make_uint4(rp[0], rp[1], rp[2], rp[3]);
            size_t gi = ((size_t)((b0 + b_loc) * 16 + n) * 1024 + c0 + c_loc) * 2 + dh;
            ug[gi] = v;
        }

        // --- consumer B: c-partial reduction -> g_part
        {
            const int b2 = t >> 3, dp2 = t & 7;
            float s0 = 0.f, s1 = 0.f;
#pragma unroll
            for (int w2 = 0; w2 < 8; w2++) {
                __half2 hv = *(__half2*)&red[w2 * RED_STRIDE + b2 * 9 + dp2];
                float2 f = __half22float2(hv);
                s0 += f.x; s1 += f.y;
            }
            *(float2*)&g_part[cblk * 32768 + (b0 + b2) * 256 + n * 16 + dp2 * 2] =
                make_float2(s0, s1);
        }
        // next iter's first sync orders red reuse
    }
}

// ---------------------------------------------------------------------------
// k_usum: grid 128 (b), 256 threads: usum[b][nd] = sum of 128 cblk partials
// ---------------------------------------------------------------------------
__global__ __launch_bounds__(256) void k_usum() {
    const int t = threadIdx.x, b = blockIdx.x;
    const float* p = g_part + b * 256 + t;
    float a0 = 0, a1 = 0, a2 = 0, a3 = 0, a4 = 0, a5 = 0, a6 = 0, a7 = 0;
#pragma unroll
    for (int k = 0; k < K1_NCBLK; k += 8) {
        a0 += p[(size_t)(k + 0) * 32768];
        a1 += p[(size_t)(k + 1) * 32768];
        a2 += p[(size_t)(k + 2) * 32768];
        a3 += p[(size_t)(k + 3) * 32768];
        a4 += p[(size_t)(k + 4) * 32768];
        a5 += p[(size_t)(k + 5) * 32768];
        a6 += p[(size_t)(k + 6) * 32768];
        a7 += p[(size_t)(k + 7) * 32768];
    }
    g_usum[b * 256 + t] = ((a0 + a1) + (a2 + a3)) + ((a4 + a5) + (a6 + a7));
}

// ---------------------------------------------------------------------------
// k2a: grid (128 b, 16 csplit), 256 threads, 2 tiles of 32 c.
// ---------------------------------------------------------------------------
__global__ __launch_bounds__(256) void k2a_route(const float* __restrict__ Bb) {
    __shared__ uint4 uhs[16 * 97];
    __shared__ float sco[544];
    __shared__ float wbf[544];

    const int t  = threadIdx.x;
    const int b  = blockIdx.x;
    const int cs = blockIdx.y;

    const int sn = t >> 4, scs = t & 15;
    float ur[16];
#pragma unroll
    for (int j = 0; j < 16; j++) ur[j] = g_usum[b * 256 + sn * 16 + j];

    const int asp = t >> 6, an = (t >> 2) & 15, adq = t & 3;
    float sacc0 = 0, sacc1 = 0, sacc2 = 0, sacc3 = 0;

    const uint4* ug = (const uint4*)g_uhat;

    int ld_nn[4], ld_cl[4], ld_dh[4];
#pragma unroll
    for (int k = 0; k < 4; k++) {
        int flat = (t + 256 * k) * 8;
        ld_nn[k] = flat >> 9;
        ld_cl[k] = (flat >> 4) & 31;
        ld_dh[k] = (flat >> 3) & 1;
    }

    uint4 pv[4];
    {
        const int cb = cs * 64;
#pragma unroll
        for (int k = 0; k < 4; k++)
            pv[k] = ug[((size_t)(b * 16 + ld_nn[k]) * 1024 + cb + ld_cl[k]) * 2 + ld_dh[k]];
    }

#pragma unroll
    for (int tile = 0; tile < K2_TILES; tile++) {
        const int cb = cs * 64 + tile * K2_CT;
        __syncthreads();

#pragma unroll
        for (int k = 0; k < 4; k++)
            uhs[ld_nn[k] * 97 + ld_cl[k] * 3 + ld_dh[k]] = pv[k];
        __syncthreads();

        if (tile + 1 < K2_TILES) {
            const int cbn = cb + K2_CT;
#pragma unroll
            for (int k = 0; k < 4; k++)
                pv[k] = ug[((size_t)(b * 16 + ld_nn[k]) * 1024 + cbn + ld_cl[k]) * 2 + ld_dh[k]];
        }

        // --- scores
#pragma unroll
        for (int p = 0; p < 2; p++) {
            int cx = scs + p * 16;
            uint4 ua = uhs[sn * 97 + cx * 3 + 0];
            uint4 ub = uhs[sn * 97 + cx * 3 + 1];
            const __half2* ha = (const __half2*)&ua;
            const __half2* hb = (const __half2*)&ub;
            float dot = 0.f;
#pragma unroll
            for (int j = 0; j < 4; j++) {
                float2 fa = __half22float2(ha[j]);
                float2 fb = __half22float2(hb[j]);
                dot += fa.x * ur[2 * j] + fa.y * ur[2 * j + 1];
                dot += fb.x * ur[8 + 2 * j] + fb.y * ur[9 + 2 * j];
            }
            sco[cx * 17 + sn] = COEF * dot;
        }
        __syncthreads();

        // --- softmax over n + add B
        if (t < 32) {
            int cx = t;
            float v[16];
            float m = -1e30f;
#pragma unroll
            for (int nn = 0; nn < 16; nn++) { v[nn] = sco[cx * 17 + nn]; m = fmaxf(m, v[nn]); }
            float s = 0.f;
#pragma unroll
            for (int nn = 0; nn < 16; nn++) { v[nn] = expf(v[nn] - m); s += v[nn]; }
            float inv = 1.0f / s;
#pragma unroll
            for (int nn = 0; nn < 16; nn++)
                wbf[cx * 17 + nn] = v[nn] * inv + Bb[nn * 1024 + cb + cx];
        }
        __syncthreads();

        // --- weighted accumulate
        const __half2* uh2 = (const __half2*)uhs;
#pragma unroll
        for (int j = 0; j < 8; j++) {
            int cc2 = asp * 8 + j;
            float wv = wbf[cc2 * 17 + an];
            int h2i = (an * 97 + cc2 * 3) * 4 + adq * 2;
            float2 f0 = __half22float2(uh2[h2i]);
            float2 f1 = __half22float2(uh2[h2i + 1]);
            sacc0 += wv * f0.x; sacc1 += wv * f0.y;
            sacc2 += wv * f1.x; sacc3 += wv * f1.y;
        }
    }
    __syncthreads();

    float* spart = (float*)uhs;
    *(float4*)&spart[asp * 256 + an * 16 + adq * 4] = make_float4(sacc0, sacc1, sacc2, sacc3);
    __syncthreads();
    g_spart[cs * 32768 + b * 256 + t] =
        spart[t] + spart[256 + t] + spart[512 + t] + spart[768 + t];
}

// ---------------------------------------------------------------------------
// k2b: reduce 16 csplits, squash, write out
// ---------------------------------------------------------------------------
__global__ __launch_bounds__(256) void k2b_finish(float* __restrict__ out) {
    __shared__ float sfin[256];
    __shared__ float scale[16];
    const int t = threadIdx.x, b = blockIdx.x;

    const float* p = g_spart + b * 256 + t;
    float a0 = 0, a1 = 0, a2 = 0, a3 = 0;
#pragma unroll
    for (int k = 0; k < K2_SPLIT; k += 4) {
        a0 += p[(k + 0) * 32768];
        a1 += p[(k + 1) * 32768];
        a2 += p[(k + 2) * 32768];
        a3 += p[(k + 3) * 32768];
    }
    sfin[t] = (a0 + a1) + (a2 + a3);
    __syncthreads();

    if (t < 16) {
        float sq = 0.f;
#pragma unroll
        for (int d = 0; d < 16; d++) { float z = sfin[t * 16 + d]; sq += z * z; }
        float norm = sqrtf(sq);
        scale[t] = (1.0f - expf(-norm)) * rsqrtf(sq + 1e-8f);
    }
    __syncthreads();

    out[b * 256 + t] = scale[t >> 4] * sfin[t];
}

// ---------------------------------------------------------------------------
extern "C" void kernel_launch(void* const* d_in, const int* in_sizes, int n_in,
                              void* d_out, int out_size) {
    const float* x = (const float*)d_in[0];
    const float* W = (const float*)d_in[1];
    const float* B = (const float*)d_in[2];
    float* out = (float*)d_out;

    k1_uhat<<<dim3(K1_NCBLK, NCAPS), 256>>>(x, W);
    k_usum<<<BATCH, 256>>>();
    k2a_route<<<dim3(BATCH, K2_SPLIT), 256>>>(B);
    k2b_finish<<<BATCH, 256>>>(out);
}